// round 1
// baseline (speedup 1.0000x reference)
#include <cuda_runtime.h>
#include <math.h>

#define T_FRAMES 40
#define HW 1024
#define NK (T_FRAMES * HW)   // 40960 keys
#define NQ 1024              // queries
#define C 64                 // channels
#define NTOP 10
#define INV_TEMP (1.0f / 0.07f)
#define NEG_BIG -1e30f
#define R2 144               // radius^2 (radius = 24/2 = 12), dist<12 <=> d2<144

// Scratch (allocation-free rule: device globals)
__device__ float g_qn[C * NQ];            // normalized query, [c][q]
__device__ float g_kn[C * NK];            // normalized key,   [c][k]
__device__ float g_S[(size_t)NQ * NK];    // scores, [q][k]  (160 MB)

// ---------------------------------------------------------------------------
// Normalization: per-position L2 norm over 64 channels (matches
// x / max(||x||, 1e-12)).
// ---------------------------------------------------------------------------
__global__ __launch_bounds__(256) void norm_key_kernel(const float* __restrict__ key) {
    int p = blockIdx.x * 256 + threadIdx.x;
    float v[C];
    float s = 0.f;
#pragma unroll
    for (int c = 0; c < C; c++) { v[c] = key[c * NK + p]; s += v[c] * v[c]; }
    float r = 1.0f / fmaxf(sqrtf(s), 1e-12f);
#pragma unroll
    for (int c = 0; c < C; c++) g_kn[c * NK + p] = v[c] * r;
}

__global__ __launch_bounds__(256) void norm_query_kernel(const float* __restrict__ q) {
    int p = blockIdx.x * 256 + threadIdx.x;
    float v[C];
    float s = 0.f;
#pragma unroll
    for (int c = 0; c < C; c++) { v[c] = q[c * NQ + p]; s += v[c] * v[c]; }
    float r = 1.0f / fmaxf(sqrtf(s), 1e-12f);
#pragma unroll
    for (int c = 0; c < C; c++) g_qn[c * NQ + p] = v[c] * r;
}

// ---------------------------------------------------------------------------
// Affinity GEMM: S[q][k] = (kn[:,k] . qn[:,q]) / TEMP, masked to -1e30 outside
// the spatial circle for frames t >= 1. Tile: 128 keys x 64 queries, full K=64.
// 256 threads, each computes a 4(q) x 8(k) micro-tile.
// Key tiles (128 | 1024) never straddle a frame boundary.
// ---------------------------------------------------------------------------
__global__ __launch_bounds__(256) void gemm_kernel() {
    __shared__ __align__(16) float ks[C * 128];   // [c][kk]  32 KB
    __shared__ __align__(16) float qs[C * 64];    // [c][qq]  16 KB

    const int tid = threadIdx.x;
    const int k0 = blockIdx.x * 128;
    const int q0 = blockIdx.y * 64;

    // cooperative loads (float4, fully coalesced)
    {
        float4* kd = (float4*)ks;
#pragma unroll
        for (int i = 0; i < 8; i++) {
            int lin = tid + i * 256;          // float4 index, 2048 total
            int c = lin >> 5;                 // 32 float4 per 128-key row
            int kk = (lin & 31) << 2;
            kd[lin] = *(const float4*)(&g_kn[c * NK + k0 + kk]);
        }
        float4* qd = (float4*)qs;
#pragma unroll
        for (int i = 0; i < 4; i++) {
            int lin = tid + i * 256;          // 1024 total
            int c = lin >> 4;                 // 16 float4 per 64-query row
            int qq = (lin & 15) << 2;
            qd[lin] = *(const float4*)(&g_qn[c * NQ + q0 + qq]);
        }
    }
    __syncthreads();

    const int tx = tid & 15;   // key direction: 16 x 8 = 128
    const int ty = tid >> 4;   // query direction: 16 x 4 = 64

    float acc[4][8];
#pragma unroll
    for (int j = 0; j < 4; j++)
#pragma unroll
        for (int i = 0; i < 8; i++) acc[j][i] = 0.f;

    const float4* ks4 = (const float4*)ks;
    const float4* qs4 = (const float4*)qs;
#pragma unroll 4
    for (int c = 0; c < C; c++) {
        float4 k1 = ks4[c * 32 + tx * 2];
        float4 k2 = ks4[c * 32 + tx * 2 + 1];
        float4 qv = qs4[c * 16 + ty];
        float kv[8] = {k1.x, k1.y, k1.z, k1.w, k2.x, k2.y, k2.z, k2.w};
        float qf[4] = {qv.x, qv.y, qv.z, qv.w};
#pragma unroll
        for (int j = 0; j < 4; j++)
#pragma unroll
            for (int i = 0; i < 8; i++)
                acc[j][i] = fmaf(qf[j], kv[i], acc[j][i]);
    }

    // epilogue: scale, geometric mask, store to S[q][k]
    const int t = k0 >> 10;                  // frame of this key tile
    const int kb = (k0 & 1023) + tx * 8;     // in-frame key base (8 keys same row)
    const int ky = kb >> 5;
    const int kxb = kb & 31;
#pragma unroll
    for (int j = 0; j < 4; j++) {
        int q = q0 + ty * 4 + j;
        float o[8];
        if (t == 0) {
#pragma unroll
            for (int i = 0; i < 8; i++) o[i] = acc[j][i] * INV_TEMP;
        } else {
            int qy = q >> 5, qx = q & 31;
            int dy = ky - qy;
            int dy2 = dy * dy;
#pragma unroll
            for (int i = 0; i < 8; i++) {
                int dx = kxb + i - qx;
                o[i] = (dy2 + dx * dx < R2) ? acc[j][i] * INV_TEMP : NEG_BIG;
            }
        }
        float* dst = g_S + (size_t)q * NK + k0 + tx * 8;
        *(float4*)dst       = make_float4(o[0], o[1], o[2], o[3]);
        *(float4*)(dst + 4) = make_float4(o[4], o[5], o[6], o[7]);
    }
}

// ---------------------------------------------------------------------------
// Per-query top-10 + softmax + value gather. One CTA (256 threads) per query.
// Thread-local sorted top-10 over a strided slice, then 10 argmax-reduction
// rounds over the 2560 candidates (ties prefer lower key index, like
// jax.lax.top_k), then softmax and output.
// ---------------------------------------------------------------------------
__global__ __launch_bounds__(256) void topk_kernel(const float* __restrict__ value,
                                                   float* __restrict__ out) {
    const int q = blockIdx.x;
    const int tid = threadIdx.x;
    const float* row = g_S + (size_t)q * NK;

    float av[NTOP];
    int ai[NTOP];
#pragma unroll
    for (int r = 0; r < NTOP; r++) { av[r] = -3.0e38f; ai[r] = 0x7fffffff; }

    for (int k = tid; k < NK; k += 256) {
        float s = row[k];
        if (s > av[NTOP - 1]) {
            av[NTOP - 1] = s; ai[NTOP - 1] = k;
#pragma unroll
            for (int r = NTOP - 1; r > 0; --r) {
                if (av[r] > av[r - 1]) {
                    float tv = av[r]; av[r] = av[r - 1]; av[r - 1] = tv;
                    int ti = ai[r];   ai[r] = ai[r - 1]; ai[r - 1] = ti;
                }
            }
        }
    }

    __shared__ float cv[256 * NTOP];
    __shared__ int   ci[256 * NTOP];
    __shared__ float rv[256];
    __shared__ int   rp[256];
    __shared__ float topv[NTOP];
    __shared__ int   topi[NTOP];
    __shared__ float w[NTOP];

#pragma unroll
    for (int r = 0; r < NTOP; r++) { cv[tid * NTOP + r] = av[r]; ci[tid * NTOP + r] = ai[r]; }
    __syncthreads();

    for (int r = 0; r < NTOP; r++) {
        float bv = cv[tid * NTOP];
        int bp = tid * NTOP;
#pragma unroll
        for (int j = 1; j < NTOP; j++) {
            int p = tid * NTOP + j;
            float v = cv[p];
            if (v > bv || (v == bv && ci[p] < ci[bp])) { bv = v; bp = p; }
        }
        rv[tid] = bv; rp[tid] = bp;
        __syncthreads();
        for (int s = 128; s > 0; s >>= 1) {
            if (tid < s) {
                float vo = rv[tid + s];
                if (vo > rv[tid] || (vo == rv[tid] && ci[rp[tid + s]] < ci[rp[tid]])) {
                    rv[tid] = vo; rp[tid] = rp[tid + s];
                }
            }
            __syncthreads();
        }
        if (tid == 0) {
            topv[r] = rv[0];
            topi[r] = ci[rp[0]];
            cv[rp[0]] = -3.0e38f;   // remove winner
        }
        __syncthreads();
    }

    if (tid == 0) {
        float m = topv[0];
        float e[NTOP];
        float sum = 0.f;
#pragma unroll
        for (int r = 0; r < NTOP; r++) { e[r] = expf(topv[r] - m); sum += e[r]; }
        float inv = 1.0f / sum;
#pragma unroll
        for (int r = 0; r < NTOP; r++) w[r] = e[r] * inv;
    }
    __syncthreads();

    if (tid < C) {
        float acc = 0.f;
#pragma unroll
        for (int r = 0; r < NTOP; r++)
            acc = fmaf(w[r], value[tid * NK + topi[r]], acc);
        out[tid * NQ + q] = acc;
    }
}

// ---------------------------------------------------------------------------
extern "C" void kernel_launch(void* const* d_in, const int* in_sizes, int n_in,
                              void* d_out, int out_size) {
    const float* query = (const float*)d_in[0];   // (1,64,32,32)
    const float* key   = (const float*)d_in[1];   // (1,64,40,32,32)
    const float* value = (const float*)d_in[2];   // (1,64,40,32,32)
    // d_in[3] (mask) unused: mask recomputed geometrically (d2 < 144)
    float* out = (float*)d_out;                   // (1,64,32,32)

    norm_query_kernel<<<NQ / 256, 256>>>(query);
    norm_key_kernel<<<NK / 256, 256>>>(key);
    dim3 grid(NK / 128, NQ / 64);
    gemm_kernel<<<grid, 256>>>();
    topk_kernel<<<NQ, 256>>>(value, out);
}